// round 7
// baseline (speedup 1.0000x reference)
#include <cuda_runtime.h>
#include <cuda_bf16.h>
#include <cstdint>

// ============================================================================
// AutoEncoder_BNN via mma.sync bf16. fp32 GEMMs emulated with K'=3K split:
//   A_cat = [A_hi | A_lo | A_hi],  B_cat = [B_hi | B_hi | B_lo]
// R5: Karatsuba mixing (3 GEMMs instead of 4).
// R7: tile 256x128x64 with 512 threads / 16 warps (warp grid 4x4, warp tile
//     64x32 = the proven R5 warp code, ~120 regs, no spills). Keeps R6's
//     2.7x-lower L2 traffic but restores R5's 16-warps-per-SM issue density.
//     3 stages x 48KB = 144KB smem, 1 CTA/SM. Batched z-launches kept.
// ============================================================================

// ---------------- device scratch (static; no runtime allocation) ------------
__device__ __nv_bfloat16 g_xcat [8192L  * 12288];
__device__ __nv_bfloat16 g_whcat[1024L  * 12288];
__device__ __nv_bfloat16 g_h1cat[8192L  * 3072];
__device__ __nv_bfloat16 g_wh2cat[1024L * 3072];
__device__ __nv_bfloat16 g_h2cat[8192L  * 3072];
__device__ __nv_bfloat16 g_wycat[4096L  * 3072];
__device__ __nv_bfloat16 g_uwcat[16384L * 6144];   // [u;w] split
__device__ __nv_bfloat16 g_sumcat[8192L * 6144];   // (u+w) split
__device__ __nv_bfloat16 g_gbmcat[4096L * 6144];   // [G;Bm] split (B-side)
__device__ __nv_bfloat16 g_gpbcat[2048L * 6144];   // (G+Bm) split (B-side)
__device__ float         g_t    [3L * 8192 * 2048]; // t1|t2|t3
__device__ __nv_bfloat16 g_ppcat[8192L  * 6144];
__device__ __nv_bfloat16 g_qpcat[8192L  * 6144];
__device__ __nv_bfloat16 g_wpcat[2048L  * 6144];
__device__ __nv_bfloat16 g_wqcat[2048L  * 6144];

// ---------------- PTX helpers ------------------------------------------------
__device__ __forceinline__ uint32_t smem_u32(const void* p) {
    uint32_t a;
    asm("{ .reg .u64 t; cvta.to.shared.u64 t, %1; cvt.u32.u64 %0, t; }" : "=r"(a) : "l"(p));
    return a;
}
__device__ __forceinline__ void cp_async16(uint32_t dst, const void* src) {
    asm volatile("cp.async.cg.shared.global [%0], [%1], 16;" :: "r"(dst), "l"(src) : "memory");
}
__device__ __forceinline__ void cp_commit() {
    asm volatile("cp.async.commit_group;" ::: "memory");
}
__device__ __forceinline__ void cp_wait1() {
    asm volatile("cp.async.wait_group 1;" ::: "memory");
}
__device__ __forceinline__ void ldsm4(uint32_t* r, uint32_t addr) {
    asm volatile("ldmatrix.sync.aligned.m8n8.x4.shared.b16 {%0,%1,%2,%3}, [%4];"
                 : "=r"(r[0]), "=r"(r[1]), "=r"(r[2]), "=r"(r[3]) : "r"(addr));
}
__device__ __forceinline__ void mma16816(float* c, const uint32_t* a, uint32_t b0, uint32_t b1) {
    asm volatile(
        "mma.sync.aligned.m16n8k16.row.col.f32.bf16.bf16.f32 "
        "{%0,%1,%2,%3}, {%4,%5,%6,%7}, {%8,%9}, {%0,%1,%2,%3};"
        : "+f"(c[0]), "+f"(c[1]), "+f"(c[2]), "+f"(c[3])
        : "r"(a[0]), "r"(a[1]), "r"(a[2]), "r"(a[3]), "r"(b0), "r"(b1));
}
__device__ __forceinline__ void split2(float a, float b, __nv_bfloat162& h, __nv_bfloat162& l) {
    __nv_bfloat16 ha = __float2bfloat16(a);
    __nv_bfloat16 hb = __float2bfloat16(b);
    h.x = ha; h.y = hb;
    l.x = __float2bfloat16(a - __bfloat162float(ha));
    l.y = __float2bfloat16(b - __bfloat162float(hb));
}

// ---------------- mma.sync GEMM, tile 256x128x64, 512 threads ----------------
// C[M,N] = act(A[M,K'] @ B[N,K']^T + bias); A,B bf16 K-major, fp32 accum.
// MODE 0: fp32 C.  MODE 1: bf16 split (hi|lo|hi) to S, stride 3*Nfull.
// MODE 2: fp32 C AND stacked u/w split into S [16384,6144].
struct GemmArgs {
    const __nv_bfloat16* A;
    const __nv_bfloat16* B;
    const float* bias;
    float* C;
    __nv_bfloat16* S;
};

constexpr int STAGE_BYTES = 49152;            // A 32KB + B 16KB
constexpr int SMEM_BYTES  = 3 * STAGE_BYTES;  // 144KB, 1 CTA/SM

template <int MODE, bool RELU, bool BIAS>
__global__ __launch_bounds__(512)
void gemm_mma(GemmArgs g0, GemmArgs g1, GemmArgs g2,
              int lda, int ldb, int ldc, int Nfull, int K)
{
    const GemmArgs& g = (blockIdx.z == 0) ? g0 : (blockIdx.z == 1) ? g1 : g2;
    extern __shared__ __align__(1024) char smem[];
    const uint32_t sb = smem_u32(smem);
    const int tid = threadIdx.x, lane = tid & 31, wid = tid >> 5;
    const int wm = wid & 3, wn = wid >> 2;            // warp grid 4(m) x 4(n)
    const int m0 = blockIdx.y * 256, n0 = blockIdx.x * 128;

    // ---- global->shared loader (16B chunks, SW128 swizzle) ----
    const int lrow = tid >> 3;        // 0..63
    const int lc16 = tid & 7;
    const uint32_t off0 = lrow * 128 + ((lc16 * 16) ^ ((lrow & 7) << 4));
    const __nv_bfloat16* Ag = g.A + (size_t)(m0 + lrow) * lda + lc16 * 8;
    const __nv_bfloat16* Bg = g.B + (size_t)(n0 + lrow) * ldb + lc16 * 8;

    // ---- ldmatrix address precompute (R5 warp-level layout) ----
    uint32_t aTerm[4], aXor[4];
#pragma unroll
    for (int mt = 0; mt < 4; ++mt) {
        const int r = wm * 64 + mt * 16 + ((lane >> 3) & 1) * 8 + (lane & 7);
        aTerm[mt] = r * 128; aXor[mt] = (r & 7) << 4;
    }
    const uint32_t aCol = (lane >> 4) * 16;
    uint32_t bTerm[2], bXor[2];
#pragma unroll
    for (int nt = 0; nt < 2; ++nt) {
        const int r = wn * 32 + nt * 16 + (lane >> 4) * 8 + (lane & 7);
        bTerm[nt] = r * 128; bXor[nt] = (r & 7) << 4;
    }
    const uint32_t bCol = ((lane >> 3) & 1) * 16;

    float acc[4][4][4];
#pragma unroll
    for (int mt = 0; mt < 4; ++mt)
#pragma unroll
        for (int n8 = 0; n8 < 4; ++n8)
#pragma unroll
            for (int j = 0; j < 4; ++j) acc[mt][n8][j] = 0.0f;

    const int nst = K / 64;

    auto issue = [&](int s, int kt) {
        const uint32_t sa = sb + (uint32_t)s * STAGE_BYTES;
#pragma unroll
        for (int p = 0; p < 4; ++p)   // A: 256 rows, 64 per pass
            cp_async16(sa + off0 + p * 8192u, Ag + (size_t)p * 64 * lda + kt);
#pragma unroll
        for (int p = 0; p < 2; ++p)   // B: 128 rows, 64 per pass
            cp_async16(sa + 32768u + off0 + p * 8192u, Bg + (size_t)p * 64 * ldb + kt);
        cp_commit();
    };

    issue(0, 0);
    issue(1, 64);

    for (int i = 0; i < nst; ++i) {
        cp_wait1();
        __syncthreads();
        if (i + 2 < nst) issue((i + 2) % 3, (i + 2) * 64);
        else             cp_commit();

        const uint32_t sa = sb + (uint32_t)(i % 3) * STAGE_BYTES;
        const uint32_t sB = sa + 32768u;
#pragma unroll
        for (int kk = 0; kk < 4; ++kk) {
            uint32_t a[4][4], b[2][4];
#pragma unroll
            for (int mt = 0; mt < 4; ++mt)
                ldsm4(a[mt], sa + aTerm[mt] + ((kk * 32 + aCol) ^ aXor[mt]));
#pragma unroll
            for (int nt = 0; nt < 2; ++nt)
                ldsm4(b[nt], sB + bTerm[nt] + ((kk * 32 + bCol) ^ bXor[nt]));
#pragma unroll
            for (int mt = 0; mt < 4; ++mt)
#pragma unroll
                for (int n8 = 0; n8 < 4; ++n8)
                    mma16816(acc[mt][n8], a[mt],
                             b[n8 >> 1][(n8 & 1) * 2], b[n8 >> 1][(n8 & 1) * 2 + 1]);
        }
        __syncthreads();
    }

    // ---- epilogue ----
    float bb[4][2];
#pragma unroll
    for (int n8 = 0; n8 < 4; ++n8) {
        if (BIAS) {
            const int col = n0 + wn * 32 + n8 * 8 + (lane & 3) * 2;
            bb[n8][0] = __ldg(&g.bias[col]);
            bb[n8][1] = __ldg(&g.bias[col + 1]);
        } else { bb[n8][0] = 0.0f; bb[n8][1] = 0.0f; }
    }

#pragma unroll
    for (int mt = 0; mt < 4; ++mt) {
#pragma unroll
        for (int half = 0; half < 2; ++half) {
            const int r = m0 + wm * 64 + mt * 16 + (lane >> 2) + half * 8;
#pragma unroll
            for (int n8 = 0; n8 < 4; ++n8) {
                const int col = n0 + wn * 32 + n8 * 8 + (lane & 3) * 2;
                float v0 = acc[mt][n8][half * 2 + 0] + bb[n8][0];
                float v1 = acc[mt][n8][half * 2 + 1] + bb[n8][1];
                if (RELU) { v0 = fmaxf(v0, 0.0f); v1 = fmaxf(v1, 0.0f); }
                if (MODE == 0 || MODE == 2)
                    *reinterpret_cast<float2*>(g.C + (size_t)r * ldc + col) = make_float2(v0, v1);
                if (MODE == 1) {
                    __nv_bfloat162 h, l; split2(v0, v1, h, l);
                    __nv_bfloat16* Sr = g.S + (size_t)r * (3 * Nfull) + col;
                    *reinterpret_cast<__nv_bfloat162*>(Sr)             = h;
                    *reinterpret_cast<__nv_bfloat162*>(Sr + Nfull)     = l;
                    *reinterpret_cast<__nv_bfloat162*>(Sr + 2 * Nfull) = h;
                }
                if (MODE == 2) {   // stacked: u rows [0,8192) | w rows [8192,16384)
                    const bool inU = (col < 2048);
                    const int rr = inU ? r : r + 8192;
                    const int cc = inU ? col : col - 2048;
                    __nv_bfloat162 h, l; split2(v0, v1, h, l);
                    __nv_bfloat16* Sr = g.S + (size_t)rr * 6144 + cc;
                    *reinterpret_cast<__nv_bfloat162*>(Sr)        = h;
                    *reinterpret_cast<__nv_bfloat162*>(Sr + 2048) = l;
                    *reinterpret_cast<__nv_bfloat162*>(Sr + 4096) = h;
                }
            }
        }
    }
}

// ------- pack: fp32 [R,C] -> bf16 split [R, 3C] -----------------------------
template <bool B_SIDE>
__global__ __launch_bounds__(256)
void pack2(const float* __restrict__ src, __nv_bfloat16* __restrict__ dst,
           int logC, long total)
{
    const long i = ((long)blockIdx.x * 256 + threadIdx.x) * 2;
    if (i >= total) return;
    const int  C = 1 << logC;
    const long r = i >> logC;
    const int  c = (int)(i & (C - 1));
    const float2 v = *reinterpret_cast<const float2*>(src + i);
    __nv_bfloat162 h, l; split2(v.x, v.y, h, l);
    __nv_bfloat16* d = dst + r * (3L * C) + c;
    if (B_SIDE) {
        *reinterpret_cast<__nv_bfloat162*>(d)         = h;
        *reinterpret_cast<__nv_bfloat162*>(d + C)     = h;
        *reinterpret_cast<__nv_bfloat162*>(d + 2 * C) = l;
    } else {
        *reinterpret_cast<__nv_bfloat162*>(d)         = h;
        *reinterpret_cast<__nv_bfloat162*>(d + C)     = l;
        *reinterpret_cast<__nv_bfloat162*>(d + 2 * C) = h;
    }
}

// ------- packadd2: (src0 + src1) -> B-side split [hi | hi | lo] --------------
__global__ __launch_bounds__(256)
void packadd2(const float* __restrict__ s0, const float* __restrict__ s1,
              __nv_bfloat16* __restrict__ dst, int logC, long total)
{
    const long i = ((long)blockIdx.x * 256 + threadIdx.x) * 2;
    if (i >= total) return;
    const int  C = 1 << logC;
    const long r = i >> logC;
    const int  c = (int)(i & (C - 1));
    const float2 a = *reinterpret_cast<const float2*>(s0 + i);
    const float2 b = *reinterpret_cast<const float2*>(s1 + i);
    __nv_bfloat162 h, l; split2(a.x + b.x, a.y + b.y, h, l);
    __nv_bfloat16* d = dst + r * (3L * C) + c;
    *reinterpret_cast<__nv_bfloat162*>(d)         = h;
    *reinterpret_cast<__nv_bfloat162*>(d + C)     = h;
    *reinterpret_cast<__nv_bfloat162*>(d + 2 * C) = l;
}

// ------- sumsplit: (u+w) from uw -> A-side split [8192, 3*2048] --------------
__global__ __launch_bounds__(256)
void sumsplit(const float* __restrict__ uw, __nv_bfloat16* __restrict__ dst)
{
    const long i = ((long)blockIdx.x * 256 + threadIdx.x) * 2;
    const long r = i >> 11;
    const int  c = (int)(i & 2047);
    const float2 u2 = *reinterpret_cast<const float2*>(uw + r * 4096 + c);
    const float2 w2 = *reinterpret_cast<const float2*>(uw + r * 4096 + 2048 + c);
    __nv_bfloat162 h, l; split2(u2.x + w2.x, u2.y + w2.y, h, l);
    __nv_bfloat16* d = dst + r * 6144 + c;
    *reinterpret_cast<__nv_bfloat162*>(d)        = h;
    *reinterpret_cast<__nv_bfloat162*>(d + 2048) = l;
    *reinterpret_cast<__nv_bfloat162*>(d + 4096) = h;
}

// ---------------- polar combine (Karatsuba) -> split pp/qp -------------------
__global__ __launch_bounds__(256)
void combine(const float* __restrict__ uw, const float* __restrict__ t,
             const float* __restrict__ bias_p, const float* __restrict__ bias_q,
             __nv_bfloat16* __restrict__ ppcat, __nv_bfloat16* __restrict__ qpcat)
{
    const long i = ((long)blockIdx.x * 256 + threadIdx.x) * 2;
    const long r = i >> 11;
    const int  c = (int)(i & 2047);
    const float2 u2 = *reinterpret_cast<const float2*>(uw + r * 4096 + c);
    const float2 w2 = *reinterpret_cast<const float2*>(uw + r * 4096 + 2048 + c);
    const float2 t1 = *reinterpret_cast<const float2*>(t + i);
    const float2 t2 = *reinterpret_cast<const float2*>(t + 8192L * 2048 + i);
    const float2 t3 = *reinterpret_cast<const float2*>(t + 2L * 8192 * 2048 + i);
    const float2 bp = *reinterpret_cast<const float2*>(bias_p + c);
    const float2 bq = *reinterpret_cast<const float2*>(bias_q + c);
    const float re0 = t1.x - t2.x, re1 = t1.y - t2.y;
    const float im0 = t3.x - t1.x - t2.x, im1 = t3.y - t1.y - t2.y;
    const float p0 = u2.x * re0 + w2.x * im0 + bp.x;
    const float p1 = u2.y * re1 + w2.y * im1 + bp.y;
    const float q0 = w2.x * re0 - u2.x * im0 + bq.x;
    const float q1 = w2.y * re1 - u2.y * im1 + bq.y;
    __nv_bfloat162 h, l;
    __nv_bfloat16* d = ppcat + r * 6144 + c;
    split2(p0, p1, h, l);
    *reinterpret_cast<__nv_bfloat162*>(d)        = h;
    *reinterpret_cast<__nv_bfloat162*>(d + 2048) = l;
    *reinterpret_cast<__nv_bfloat162*>(d + 4096) = h;
    d = qpcat + r * 6144 + c;
    split2(q0, q1, h, l);
    *reinterpret_cast<__nv_bfloat162*>(d)        = h;
    *reinterpret_cast<__nv_bfloat162*>(d + 2048) = l;
    *reinterpret_cast<__nv_bfloat162*>(d + 4096) = h;
}

// ---------------- host side --------------------------------------------------
extern "C" void kernel_launch(void* const* d_in, const int* in_sizes, int n_in,
                              void* d_out, int out_size)
{
    const float* x      = (const float*)d_in[0];
    const float* W_h    = (const float*)d_in[1];
    const float* b_h    = (const float*)d_in[2];
    const float* W_h2   = (const float*)d_in[3];
    const float* b_h2   = (const float*)d_in[4];
    const float* W_y    = (const float*)d_in[5];
    const float* b_y    = (const float*)d_in[6];
    const float* G      = (const float*)d_in[7];
    const float* Bm     = (const float*)d_in[8];
    const float* bias_p = (const float*)d_in[9];
    const float* bias_q = (const float*)d_in[10];
    const float* W_p    = (const float*)d_in[11];
    const float* b_p    = (const float*)d_in[12];
    const float* W_q    = (const float*)d_in[13];
    const float* b_q    = (const float*)d_in[14];

    float* out = (float*)d_out;
    float* uw  = out;
    float* p   = out + (size_t)8192 * 4096;
    float* q   = p   + (size_t)8192 * 2048;

    __nv_bfloat16 *xcat, *whcat, *h1cat, *wh2cat, *h2cat, *wycat, *uwcat,
                  *sumcat, *gbmcat, *gpbcat, *ppcat, *qpcat, *wpcat, *wqcat;
    float* t;
    cudaGetSymbolAddress((void**)&xcat,  g_xcat);
    cudaGetSymbolAddress((void**)&whcat, g_whcat);
    cudaGetSymbolAddress((void**)&h1cat, g_h1cat);
    cudaGetSymbolAddress((void**)&wh2cat,g_wh2cat);
    cudaGetSymbolAddress((void**)&h2cat, g_h2cat);
    cudaGetSymbolAddress((void**)&wycat, g_wycat);
    cudaGetSymbolAddress((void**)&uwcat, g_uwcat);
    cudaGetSymbolAddress((void**)&sumcat,g_sumcat);
    cudaGetSymbolAddress((void**)&gbmcat,g_gbmcat);
    cudaGetSymbolAddress((void**)&gpbcat,g_gpbcat);
    cudaGetSymbolAddress((void**)&t,     g_t);
    cudaGetSymbolAddress((void**)&ppcat, g_ppcat);
    cudaGetSymbolAddress((void**)&qpcat, g_qpcat);
    cudaGetSymbolAddress((void**)&wpcat, g_wpcat);
    cudaGetSymbolAddress((void**)&wqcat, g_wqcat);

    cudaFuncSetAttribute(gemm_mma<1, true,  true >, cudaFuncAttributeMaxDynamicSharedMemorySize, SMEM_BYTES);
    cudaFuncSetAttribute(gemm_mma<2, false, true >, cudaFuncAttributeMaxDynamicSharedMemorySize, SMEM_BYTES);
    cudaFuncSetAttribute(gemm_mma<0, false, false>, cudaFuncAttributeMaxDynamicSharedMemorySize, SMEM_BYTES);
    cudaFuncSetAttribute(gemm_mma<0, false, true >, cudaFuncAttributeMaxDynamicSharedMemorySize, SMEM_BYTES);

    // ---- packs: x is A-side [hi|lo|hi]; all weights are B-side [hi|hi|lo] ----
    pack2<false><<<(8192L * 4096 / 2 + 255) / 256, 256>>>(x,    xcat,   12, 8192L * 4096);
    pack2<true ><<<(1024L * 4096 / 2 + 255) / 256, 256>>>(W_h,  whcat,  12, 1024L * 4096);
    pack2<true ><<<(1024L * 1024 / 2 + 255) / 256, 256>>>(W_h2, wh2cat, 10, 1024L * 1024);
    pack2<true ><<<(4096L * 1024 / 2 + 255) / 256, 256>>>(W_y,  wycat,  10, 4096L * 1024);
    pack2<true ><<<(2048L * 2048 / 2 + 255) / 256, 256>>>(G,    gbmcat,                11, 2048L * 2048);
    pack2<true ><<<(2048L * 2048 / 2 + 255) / 256, 256>>>(Bm,   gbmcat + 2048L * 6144, 11, 2048L * 2048);
    packadd2   <<<(2048L * 2048 / 2 + 255) / 256, 256>>>(G, Bm, gpbcat, 11, 2048L * 2048);
    pack2<true ><<<(2048L * 2048 / 2 + 255) / 256, 256>>>(W_p,  wpcat,  11, 2048L * 2048);
    pack2<true ><<<(2048L * 2048 / 2 + 255) / 256, 256>>>(W_q,  wqcat,  11, 2048L * 2048);

    const dim3 blk(512);
    // G1: h1 = relu(x @ W_h^T + b_h) -> split h1cat
    {
        GemmArgs a{xcat, whcat, b_h, nullptr, h1cat};
        gemm_mma<1, true, true><<<dim3(1024 / 128, 8192 / 256, 1), blk, SMEM_BYTES>>>(
            a, a, a, 12288, 12288, 0, 1024, 12288);
    }
    // G2: h2 = relu(h1 @ W_h2^T + b_h2) -> split h2cat
    {
        GemmArgs a{h1cat, wh2cat, b_h2, nullptr, h2cat};
        gemm_mma<1, true, true><<<dim3(1024 / 128, 8192 / 256, 1), blk, SMEM_BYTES>>>(
            a, a, a, 3072, 3072, 0, 1024, 3072);
    }
    // G3: uw = h2 @ W_y^T + b_y -> f32 uw (d_out) + stacked split uwcat
    {
        GemmArgs a{h2cat, wycat, b_y, uw, uwcat};
        gemm_mma<2, false, true><<<dim3(4096 / 128, 8192 / 256, 1), blk, SMEM_BYTES>>>(
            a, a, a, 3072, 3072, 4096, 4096, 3072);
    }
    // (u+w) split for Karatsuba
    sumsplit<<<(8192L * 2048 / 2) / 256, 256>>>(uw, sumcat);
    // Karatsuba mixing: t1 = u@G^T, t2 = w@Bm^T, t3 = (u+w)@(G+Bm)^T (one launch)
    {
        GemmArgs a0{uwcat,                gbmcat,                nullptr, t,                    nullptr};
        GemmArgs a1{uwcat + 8192L * 6144, gbmcat + 2048L * 6144, nullptr, t + 8192L * 2048,     nullptr};
        GemmArgs a2{sumcat,               gpbcat,                nullptr, t + 2L * 8192 * 2048, nullptr};
        gemm_mma<0, false, false><<<dim3(2048 / 128, 8192 / 256, 3), blk, SMEM_BYTES>>>(
            a0, a1, a2, 6144, 6144, 2048, 2048, 6144);
    }
    // combine -> split pp/qp
    combine<<<(8192L * 2048 / 2) / 256, 256>>>(uw, t, bias_p, bias_q, ppcat, qpcat);
    // G5/G6: final projections (one launch)
    {
        GemmArgs a0{ppcat, wpcat, b_p, p, nullptr};
        GemmArgs a1{qpcat, wqcat, b_q, q, nullptr};
        gemm_mma<0, false, true><<<dim3(2048 / 128, 8192 / 256, 2), blk, SMEM_BYTES>>>(
            a0, a1, a0, 6144, 6144, 2048, 2048, 6144);
    }
}

// round 8
// speedup vs baseline: 1.1660x; 1.1660x over previous
#include <cuda_runtime.h>
#include <cuda_bf16.h>
#include <cstdint>

// ============================================================================
// AutoEncoder_BNN via mma.sync bf16. fp32 GEMMs emulated with K'=3K split:
//   A_cat = [A_hi | A_lo | A_hi],  B_cat = [B_hi | B_hi | B_lo]
// R5: Karatsuba mixing (3 GEMMs instead of 4).
// R8: engine reverted to the proven R5 config (128x128x64 tile, 256 thr,
//     3x32KB stages, 2 CTAs/SM — R6/R7 showed inter-CTA overlap beats lower
//     L2 traffic). Kept from R6: z-batched launches for mix (z=3) and final
//     (z=2) GEMMs to remove wave-quantization tails.
// ============================================================================

// ---------------- device scratch (static; no runtime allocation) ------------
__device__ __nv_bfloat16 g_xcat [8192L  * 12288];
__device__ __nv_bfloat16 g_whcat[1024L  * 12288];
__device__ __nv_bfloat16 g_h1cat[8192L  * 3072];
__device__ __nv_bfloat16 g_wh2cat[1024L * 3072];
__device__ __nv_bfloat16 g_h2cat[8192L  * 3072];
__device__ __nv_bfloat16 g_wycat[4096L  * 3072];
__device__ __nv_bfloat16 g_uwcat[16384L * 6144];   // [u;w] split
__device__ __nv_bfloat16 g_sumcat[8192L * 6144];   // (u+w) split
__device__ __nv_bfloat16 g_gbmcat[4096L * 6144];   // [G;Bm] split (B-side)
__device__ __nv_bfloat16 g_gpbcat[2048L * 6144];   // (G+Bm) split (B-side)
__device__ float         g_t    [3L * 8192 * 2048]; // t1|t2|t3
__device__ __nv_bfloat16 g_ppcat[8192L  * 6144];
__device__ __nv_bfloat16 g_qpcat[8192L  * 6144];
__device__ __nv_bfloat16 g_wpcat[2048L  * 6144];
__device__ __nv_bfloat16 g_wqcat[2048L  * 6144];

// ---------------- PTX helpers ------------------------------------------------
__device__ __forceinline__ uint32_t smem_u32(const void* p) {
    uint32_t a;
    asm("{ .reg .u64 t; cvta.to.shared.u64 t, %1; cvt.u32.u64 %0, t; }" : "=r"(a) : "l"(p));
    return a;
}
__device__ __forceinline__ void cp_async16(uint32_t dst, const void* src) {
    asm volatile("cp.async.cg.shared.global [%0], [%1], 16;" :: "r"(dst), "l"(src) : "memory");
}
__device__ __forceinline__ void cp_commit() {
    asm volatile("cp.async.commit_group;" ::: "memory");
}
__device__ __forceinline__ void cp_wait1() {
    asm volatile("cp.async.wait_group 1;" ::: "memory");
}
__device__ __forceinline__ void ldsm4(uint32_t* r, uint32_t addr) {
    asm volatile("ldmatrix.sync.aligned.m8n8.x4.shared.b16 {%0,%1,%2,%3}, [%4];"
                 : "=r"(r[0]), "=r"(r[1]), "=r"(r[2]), "=r"(r[3]) : "r"(addr));
}
__device__ __forceinline__ void mma16816(float* c, const uint32_t* a, uint32_t b0, uint32_t b1) {
    asm volatile(
        "mma.sync.aligned.m16n8k16.row.col.f32.bf16.bf16.f32 "
        "{%0,%1,%2,%3}, {%4,%5,%6,%7}, {%8,%9}, {%0,%1,%2,%3};"
        : "+f"(c[0]), "+f"(c[1]), "+f"(c[2]), "+f"(c[3])
        : "r"(a[0]), "r"(a[1]), "r"(a[2]), "r"(a[3]), "r"(b0), "r"(b1));
}
__device__ __forceinline__ void split2(float a, float b, __nv_bfloat162& h, __nv_bfloat162& l) {
    __nv_bfloat16 ha = __float2bfloat16(a);
    __nv_bfloat16 hb = __float2bfloat16(b);
    h.x = ha; h.y = hb;
    l.x = __float2bfloat16(a - __bfloat162float(ha));
    l.y = __float2bfloat16(b - __bfloat162float(hb));
}

// ---------------- mma.sync GEMM, tile 128x128x64, 256 threads (R5) -----------
// C[M,N] = act(A[M,K'] @ B[N,K']^T + bias); A,B bf16 K-major, fp32 accum.
// MODE 0: fp32 C.  MODE 1: bf16 split (hi|lo|hi) to S, stride 3*Nfull.
// MODE 2: fp32 C AND stacked u/w split into S [16384,6144].
struct GemmArgs {
    const __nv_bfloat16* A;
    const __nv_bfloat16* B;
    const float* bias;
    float* C;
    __nv_bfloat16* S;
};

constexpr int SMEM_BYTES = 3 * 32768;   // 3 stages x (A 16KB + B 16KB)

template <int MODE, bool RELU, bool BIAS>
__global__ __launch_bounds__(256, 2)
void gemm_mma(GemmArgs g0, GemmArgs g1, GemmArgs g2,
              int lda, int ldb, int ldc, int Nfull, int K)
{
    const GemmArgs& g = (blockIdx.z == 0) ? g0 : (blockIdx.z == 1) ? g1 : g2;
    extern __shared__ __align__(1024) char smem[];
    const uint32_t sb = smem_u32(smem);
    const int tid = threadIdx.x, lane = tid & 31, wid = tid >> 5;
    const int wm = wid & 1, wn = wid >> 1;            // warp grid 2(m) x 4(n)
    const int m0 = blockIdx.y * 128, n0 = blockIdx.x * 128;

    // ---- global->shared loader mapping (16B chunks, SW128 swizzle) ----
    const int lrow = tid >> 3;        // 0..31 (4 waves of 32 rows)
    const int lc16 = tid & 7;         // 16B chunk within 128B row
    uint32_t ld_off[4];
#pragma unroll
    for (int w2 = 0; w2 < 4; ++w2) {
        const int r = lrow + w2 * 32;
        ld_off[w2] = r * 128 + ((lc16 * 16) ^ ((r & 7) << 4));
    }
    const __nv_bfloat16* Ag = g.A + (size_t)(m0 + lrow) * lda + lc16 * 8;
    const __nv_bfloat16* Bg = g.B + (size_t)(n0 + lrow) * ldb + lc16 * 8;

    // ---- ldmatrix address precompute ----
    uint32_t aTerm[4], aXor[4];
#pragma unroll
    for (int mt = 0; mt < 4; ++mt) {
        const int r = wm * 64 + mt * 16 + ((lane >> 3) & 1) * 8 + (lane & 7);
        aTerm[mt] = r * 128; aXor[mt] = (r & 7) << 4;
    }
    const uint32_t aCol = (lane >> 4) * 16;
    uint32_t bTerm[2], bXor[2];
#pragma unroll
    for (int nt = 0; nt < 2; ++nt) {
        const int r = wn * 32 + nt * 16 + (lane >> 4) * 8 + (lane & 7);
        bTerm[nt] = r * 128; bXor[nt] = (r & 7) << 4;
    }
    const uint32_t bCol = ((lane >> 3) & 1) * 16;

    float acc[4][4][4];
#pragma unroll
    for (int mt = 0; mt < 4; ++mt)
#pragma unroll
        for (int n8 = 0; n8 < 4; ++n8)
#pragma unroll
            for (int j = 0; j < 4; ++j) acc[mt][n8][j] = 0.0f;

    const int nst = K / 64;

    auto issue = [&](int s, int kt) {
        const uint32_t sa = sb + (uint32_t)s * 32768u;
#pragma unroll
        for (int w2 = 0; w2 < 4; ++w2)
            cp_async16(sa + ld_off[w2], Ag + (size_t)w2 * 32 * lda + kt);
#pragma unroll
        for (int w2 = 0; w2 < 4; ++w2)
            cp_async16(sa + 16384u + ld_off[w2], Bg + (size_t)w2 * 32 * ldb + kt);
        cp_commit();
    };

    issue(0, 0);
    issue(1, 64);

    for (int i = 0; i < nst; ++i) {
        cp_wait1();
        __syncthreads();
        if (i + 2 < nst) issue((i + 2) % 3, (i + 2) * 64);
        else             cp_commit();            // keep group counting uniform

        const uint32_t sa = sb + (uint32_t)(i % 3) * 32768u;
        const uint32_t sB = sa + 16384u;
#pragma unroll
        for (int kk = 0; kk < 4; ++kk) {
            uint32_t a[4][4], b[2][4];
#pragma unroll
            for (int mt = 0; mt < 4; ++mt)
                ldsm4(a[mt], sa + aTerm[mt] + ((kk * 32 + aCol) ^ aXor[mt]));
#pragma unroll
            for (int nt = 0; nt < 2; ++nt)
                ldsm4(b[nt], sB + bTerm[nt] + ((kk * 32 + bCol) ^ bXor[nt]));
#pragma unroll
            for (int mt = 0; mt < 4; ++mt)
#pragma unroll
                for (int n8 = 0; n8 < 4; ++n8)
                    mma16816(acc[mt][n8], a[mt],
                             b[n8 >> 1][(n8 & 1) * 2], b[n8 >> 1][(n8 & 1) * 2 + 1]);
        }
        __syncthreads();
    }

    // ---- epilogue ----
    float bb[4][2];
#pragma unroll
    for (int n8 = 0; n8 < 4; ++n8) {
        if (BIAS) {
            const int col = n0 + wn * 32 + n8 * 8 + (lane & 3) * 2;
            bb[n8][0] = __ldg(&g.bias[col]);
            bb[n8][1] = __ldg(&g.bias[col + 1]);
        } else { bb[n8][0] = 0.0f; bb[n8][1] = 0.0f; }
    }

#pragma unroll
    for (int mt = 0; mt < 4; ++mt) {
#pragma unroll
        for (int half = 0; half < 2; ++half) {
            const int r = m0 + wm * 64 + mt * 16 + (lane >> 2) + half * 8;
#pragma unroll
            for (int n8 = 0; n8 < 4; ++n8) {
                const int col = n0 + wn * 32 + n8 * 8 + (lane & 3) * 2;
                float v0 = acc[mt][n8][half * 2 + 0] + bb[n8][0];
                float v1 = acc[mt][n8][half * 2 + 1] + bb[n8][1];
                if (RELU) { v0 = fmaxf(v0, 0.0f); v1 = fmaxf(v1, 0.0f); }
                if (MODE == 0 || MODE == 2)
                    *reinterpret_cast<float2*>(g.C + (size_t)r * ldc + col) = make_float2(v0, v1);
                if (MODE == 1) {
                    __nv_bfloat162 h, l; split2(v0, v1, h, l);
                    __nv_bfloat16* Sr = g.S + (size_t)r * (3 * Nfull) + col;
                    *reinterpret_cast<__nv_bfloat162*>(Sr)             = h;
                    *reinterpret_cast<__nv_bfloat162*>(Sr + Nfull)     = l;
                    *reinterpret_cast<__nv_bfloat162*>(Sr + 2 * Nfull) = h;
                }
                if (MODE == 2) {   // stacked: u rows [0,8192) | w rows [8192,16384)
                    const bool inU = (col < 2048);
                    const int rr = inU ? r : r + 8192;
                    const int cc = inU ? col : col - 2048;
                    __nv_bfloat162 h, l; split2(v0, v1, h, l);
                    __nv_bfloat16* Sr = g.S + (size_t)rr * 6144 + cc;
                    *reinterpret_cast<__nv_bfloat162*>(Sr)        = h;
                    *reinterpret_cast<__nv_bfloat162*>(Sr + 2048) = l;
                    *reinterpret_cast<__nv_bfloat162*>(Sr + 4096) = h;
                }
            }
        }
    }
}

// ------- pack: fp32 [R,C] -> bf16 split [R, 3C] -----------------------------
template <bool B_SIDE>
__global__ __launch_bounds__(256)
void pack2(const float* __restrict__ src, __nv_bfloat16* __restrict__ dst,
           int logC, long total)
{
    const long i = ((long)blockIdx.x * 256 + threadIdx.x) * 2;
    if (i >= total) return;
    const int  C = 1 << logC;
    const long r = i >> logC;
    const int  c = (int)(i & (C - 1));
    const float2 v = *reinterpret_cast<const float2*>(src + i);
    __nv_bfloat162 h, l; split2(v.x, v.y, h, l);
    __nv_bfloat16* d = dst + r * (3L * C) + c;
    if (B_SIDE) {
        *reinterpret_cast<__nv_bfloat162*>(d)         = h;
        *reinterpret_cast<__nv_bfloat162*>(d + C)     = h;
        *reinterpret_cast<__nv_bfloat162*>(d + 2 * C) = l;
    } else {
        *reinterpret_cast<__nv_bfloat162*>(d)         = h;
        *reinterpret_cast<__nv_bfloat162*>(d + C)     = l;
        *reinterpret_cast<__nv_bfloat162*>(d + 2 * C) = h;
    }
}

// ------- packadd2: (src0 + src1) -> B-side split [hi | hi | lo] --------------
__global__ __launch_bounds__(256)
void packadd2(const float* __restrict__ s0, const float* __restrict__ s1,
              __nv_bfloat16* __restrict__ dst, int logC, long total)
{
    const long i = ((long)blockIdx.x * 256 + threadIdx.x) * 2;
    if (i >= total) return;
    const int  C = 1 << logC;
    const long r = i >> logC;
    const int  c = (int)(i & (C - 1));
    const float2 a = *reinterpret_cast<const float2*>(s0 + i);
    const float2 b = *reinterpret_cast<const float2*>(s1 + i);
    __nv_bfloat162 h, l; split2(a.x + b.x, a.y + b.y, h, l);
    __nv_bfloat16* d = dst + r * (3L * C) + c;
    *reinterpret_cast<__nv_bfloat162*>(d)         = h;
    *reinterpret_cast<__nv_bfloat162*>(d + C)     = h;
    *reinterpret_cast<__nv_bfloat162*>(d + 2 * C) = l;
}

// ------- sumsplit: (u+w) from uw -> A-side split [8192, 3*2048] --------------
__global__ __launch_bounds__(256)
void sumsplit(const float* __restrict__ uw, __nv_bfloat16* __restrict__ dst)
{
    const long i = ((long)blockIdx.x * 256 + threadIdx.x) * 2;
    const long r = i >> 11;
    const int  c = (int)(i & 2047);
    const float2 u2 = *reinterpret_cast<const float2*>(uw + r * 4096 + c);
    const float2 w2 = *reinterpret_cast<const float2*>(uw + r * 4096 + 2048 + c);
    __nv_bfloat162 h, l; split2(u2.x + w2.x, u2.y + w2.y, h, l);
    __nv_bfloat16* d = dst + r * 6144 + c;
    *reinterpret_cast<__nv_bfloat162*>(d)        = h;
    *reinterpret_cast<__nv_bfloat162*>(d + 2048) = l;
    *reinterpret_cast<__nv_bfloat162*>(d + 4096) = h;
}

// ---------------- polar combine (Karatsuba) -> split pp/qp -------------------
__global__ __launch_bounds__(256)
void combine(const float* __restrict__ uw, const float* __restrict__ t,
             const float* __restrict__ bias_p, const float* __restrict__ bias_q,
             __nv_bfloat16* __restrict__ ppcat, __nv_bfloat16* __restrict__ qpcat)
{
    const long i = ((long)blockIdx.x * 256 + threadIdx.x) * 2;
    const long r = i >> 11;
    const int  c = (int)(i & 2047);
    const float2 u2 = *reinterpret_cast<const float2*>(uw + r * 4096 + c);
    const float2 w2 = *reinterpret_cast<const float2*>(uw + r * 4096 + 2048 + c);
    const float2 t1 = *reinterpret_cast<const float2*>(t + i);
    const float2 t2 = *reinterpret_cast<const float2*>(t + 8192L * 2048 + i);
    const float2 t3 = *reinterpret_cast<const float2*>(t + 2L * 8192 * 2048 + i);
    const float2 bp = *reinterpret_cast<const float2*>(bias_p + c);
    const float2 bq = *reinterpret_cast<const float2*>(bias_q + c);
    const float re0 = t1.x - t2.x, re1 = t1.y - t2.y;
    const float im0 = t3.x - t1.x - t2.x, im1 = t3.y - t1.y - t2.y;
    const float p0 = u2.x * re0 + w2.x * im0 + bp.x;
    const float p1 = u2.y * re1 + w2.y * im1 + bp.y;
    const float q0 = w2.x * re0 - u2.x * im0 + bq.x;
    const float q1 = w2.y * re1 - u2.y * im1 + bq.y;
    __nv_bfloat162 h, l;
    __nv_bfloat16* d = ppcat + r * 6144 + c;
    split2(p0, p1, h, l);
    *reinterpret_cast<__nv_bfloat162*>(d)        = h;
    *reinterpret_cast<__nv_bfloat162*>(d + 2048) = l;
    *reinterpret_cast<__nv_bfloat162*>(d + 4096) = h;
    d = qpcat + r * 6144 + c;
    split2(q0, q1, h, l);
    *reinterpret_cast<__nv_bfloat162*>(d)        = h;
    *reinterpret_cast<__nv_bfloat162*>(d + 2048) = l;
    *reinterpret_cast<__nv_bfloat162*>(d + 4096) = h;
}

// ---------------- host side --------------------------------------------------
extern "C" void kernel_launch(void* const* d_in, const int* in_sizes, int n_in,
                              void* d_out, int out_size)
{
    const float* x      = (const float*)d_in[0];
    const float* W_h    = (const float*)d_in[1];
    const float* b_h    = (const float*)d_in[2];
    const float* W_h2   = (const float*)d_in[3];
    const float* b_h2   = (const float*)d_in[4];
    const float* W_y    = (const float*)d_in[5];
    const float* b_y    = (const float*)d_in[6];
    const float* G      = (const float*)d_in[7];
    const float* Bm     = (const float*)d_in[8];
    const float* bias_p = (const float*)d_in[9];
    const float* bias_q = (const float*)d_in[10];
    const float* W_p    = (const float*)d_in[11];
    const float* b_p    = (const float*)d_in[12];
    const float* W_q    = (const float*)d_in[13];
    const float* b_q    = (const float*)d_in[14];

    float* out = (float*)d_out;
    float* uw  = out;
    float* p   = out + (size_t)8192 * 4096;
    float* q   = p   + (size_t)8192 * 2048;

    __nv_bfloat16 *xcat, *whcat, *h1cat, *wh2cat, *h2cat, *wycat, *uwcat,
                  *sumcat, *gbmcat, *gpbcat, *ppcat, *qpcat, *wpcat, *wqcat;
    float* t;
    cudaGetSymbolAddress((void**)&xcat,  g_xcat);
    cudaGetSymbolAddress((void**)&whcat, g_whcat);
    cudaGetSymbolAddress((void**)&h1cat, g_h1cat);
    cudaGetSymbolAddress((void**)&wh2cat,g_wh2cat);
    cudaGetSymbolAddress((void**)&h2cat, g_h2cat);
    cudaGetSymbolAddress((void**)&wycat, g_wycat);
    cudaGetSymbolAddress((void**)&uwcat, g_uwcat);
    cudaGetSymbolAddress((void**)&sumcat,g_sumcat);
    cudaGetSymbolAddress((void**)&gbmcat,g_gbmcat);
    cudaGetSymbolAddress((void**)&gpbcat,g_gpbcat);
    cudaGetSymbolAddress((void**)&t,     g_t);
    cudaGetSymbolAddress((void**)&ppcat, g_ppcat);
    cudaGetSymbolAddress((void**)&qpcat, g_qpcat);
    cudaGetSymbolAddress((void**)&wpcat, g_wpcat);
    cudaGetSymbolAddress((void**)&wqcat, g_wqcat);

    cudaFuncSetAttribute(gemm_mma<1, true,  true >, cudaFuncAttributeMaxDynamicSharedMemorySize, SMEM_BYTES);
    cudaFuncSetAttribute(gemm_mma<2, false, true >, cudaFuncAttributeMaxDynamicSharedMemorySize, SMEM_BYTES);
    cudaFuncSetAttribute(gemm_mma<0, false, false>, cudaFuncAttributeMaxDynamicSharedMemorySize, SMEM_BYTES);
    cudaFuncSetAttribute(gemm_mma<0, false, true >, cudaFuncAttributeMaxDynamicSharedMemorySize, SMEM_BYTES);

    // ---- packs: x is A-side [hi|lo|hi]; all weights are B-side [hi|hi|lo] ----
    pack2<false><<<(8192L * 4096 / 2 + 255) / 256, 256>>>(x,    xcat,   12, 8192L * 4096);
    pack2<true ><<<(1024L * 4096 / 2 + 255) / 256, 256>>>(W_h,  whcat,  12, 1024L * 4096);
    pack2<true ><<<(1024L * 1024 / 2 + 255) / 256, 256>>>(W_h2, wh2cat, 10, 1024L * 1024);
    pack2<true ><<<(4096L * 1024 / 2 + 255) / 256, 256>>>(W_y,  wycat,  10, 4096L * 1024);
    pack2<true ><<<(2048L * 2048 / 2 + 255) / 256, 256>>>(G,    gbmcat,                11, 2048L * 2048);
    pack2<true ><<<(2048L * 2048 / 2 + 255) / 256, 256>>>(Bm,   gbmcat + 2048L * 6144, 11, 2048L * 2048);
    packadd2   <<<(2048L * 2048 / 2 + 255) / 256, 256>>>(G, Bm, gpbcat, 11, 2048L * 2048);
    pack2<true ><<<(2048L * 2048 / 2 + 255) / 256, 256>>>(W_p,  wpcat,  11, 2048L * 2048);
    pack2<true ><<<(2048L * 2048 / 2 + 255) / 256, 256>>>(W_q,  wqcat,  11, 2048L * 2048);

    const dim3 blk(256);
    // G1: h1 = relu(x @ W_h^T + b_h) -> split h1cat
    {
        GemmArgs a{xcat, whcat, b_h, nullptr, h1cat};
        gemm_mma<1, true, true><<<dim3(1024 / 128, 8192 / 128, 1), blk, SMEM_BYTES>>>(
            a, a, a, 12288, 12288, 0, 1024, 12288);
    }
    // G2: h2 = relu(h1 @ W_h2^T + b_h2) -> split h2cat
    {
        GemmArgs a{h1cat, wh2cat, b_h2, nullptr, h2cat};
        gemm_mma<1, true, true><<<dim3(1024 / 128, 8192 / 128, 1), blk, SMEM_BYTES>>>(
            a, a, a, 3072, 3072, 0, 1024, 3072);
    }
    // G3: uw = h2 @ W_y^T + b_y -> f32 uw (d_out) + stacked split uwcat
    {
        GemmArgs a{h2cat, wycat, b_y, uw, uwcat};
        gemm_mma<2, false, true><<<dim3(4096 / 128, 8192 / 128, 1), blk, SMEM_BYTES>>>(
            a, a, a, 3072, 3072, 4096, 4096, 3072);
    }
    // (u+w) split for Karatsuba
    sumsplit<<<(8192L * 2048 / 2) / 256, 256>>>(uw, sumcat);
    // Karatsuba mixing: t1 = u@G^T, t2 = w@Bm^T, t3 = (u+w)@(G+Bm)^T (one launch)
    {
        GemmArgs a0{uwcat,                gbmcat,                nullptr, t,                    nullptr};
        GemmArgs a1{uwcat + 8192L * 6144, gbmcat + 2048L * 6144, nullptr, t + 8192L * 2048,     nullptr};
        GemmArgs a2{sumcat,               gpbcat,                nullptr, t + 2L * 8192 * 2048, nullptr};
        gemm_mma<0, false, false><<<dim3(2048 / 128, 8192 / 128, 3), blk, SMEM_BYTES>>>(
            a0, a1, a2, 6144, 6144, 2048, 2048, 6144);
    }
    // combine -> split pp/qp
    combine<<<(8192L * 2048 / 2) / 256, 256>>>(uw, t, bias_p, bias_q, ppcat, qpcat);
    // G5/G6: final projections (one launch)
    {
        GemmArgs a0{ppcat, wpcat, b_p, p, nullptr};
        GemmArgs a1{qpcat, wqcat, b_q, q, nullptr};
        gemm_mma<0, false, true><<<dim3(2048 / 128, 8192 / 128, 2), blk, SMEM_BYTES>>>(
            a0, a1, a0, 6144, 6144, 2048, 2048, 6144);
    }
}